// round 1
// baseline (speedup 1.0000x reference)
#include <cuda_runtime.h>
#include <math.h>

// Problem constants
#define Bc   8
#define Sc   512
#define Dc   1024
#define Oc   1024
#define Tc   12
#define DEPc 3
#define Lc   8
#define Mrows (Bc*Sc)          // 4096
#define NCOLS 48               // 36 decision + 12 gate
#define DECAYF 0.9f
#define ONE_M_DECAY 0.1f

// ------------------------------------------------------------------
// Scratch (allocation-free: device globals)
// ------------------------------------------------------------------
__device__ float g_ema[Mrows * Dc];    // 16 MB
__device__ float g_rout[Mrows * Dc];   // 16 MB
__device__ float g_q[Mrows * 96];      // 1.5 MB

__device__ __forceinline__ float softplusf(float v) {
    return (v > 20.f) ? v : log1pf(expf(v));
}

// ------------------------------------------------------------------
// K1: causal EMA.  one thread per (b,d), serial over S.
// ema[b,s,d] = 0.1 * sum_{j=1..s} x[b,j-1,d]*0.9^j / (0.9^s + 1e-8)
// ------------------------------------------------------------------
__global__ void ema_kernel(const float* __restrict__ x)
{
    int d = blockIdx.x * blockDim.x + threadIdx.x;   // 0..1023
    int b = blockIdx.y;
    const float* xp = x + (size_t)b * Sc * Dc + d;
    float*       ep = g_ema + (size_t)b * Sc * Dc + d;

    float c = 0.f;
    float p = 1.0f;          // 0.9^s
    ep[0] = 0.f;
    #pragma unroll 4
    for (int s = 1; s < Sc; ++s) {
        p *= DECAYF;
        c += xp[(size_t)(s - 1) * Dc] * p;
        ep[(size_t)s * Dc] = ONE_M_DECAY * c / (p + 1e-8f);
    }
}

// ------------------------------------------------------------------
// K2: routing = ema @ cW + x + cb   (M=4096, N=1024, K=1024)
// classic 128x128x16 sgemm, 256 threads, 8x8 per thread
// ------------------------------------------------------------------
#define BM 128
#define BN 128
#define BK 16
#define TM 8
#define TN 8

__global__ __launch_bounds__(256) void sgemm_routing(
    const float* __restrict__ Bw,    // cW [K,N] row-major
    const float* __restrict__ X,     // x  [M,N]
    const float* __restrict__ bias)  // cb [N]
{
    __shared__ float As[BK][BM];
    __shared__ float Bs[BK][BN];

    const int tid  = threadIdx.x;
    const int brow = blockIdx.y * BM;
    const int bcol = blockIdx.x * BN;
    const int tcol = (tid % (BN / TN)) * TN;
    const int trow = (tid / (BN / TN)) * TM;

    const float* A = g_rout ? g_ema : g_ema; // (keep compiler honest; A = g_ema)

    float acc[TM][TN];
    #pragma unroll
    for (int i = 0; i < TM; ++i)
        #pragma unroll
        for (int j = 0; j < TN; ++j) acc[i][j] = 0.f;

    const int K = Dc, N = Oc;

    for (int k0 = 0; k0 < K; k0 += BK) {
        // A tile: 128x16 -> 512 float4, 2 per thread, store transposed
        #pragma unroll
        for (int t = 0; t < 2; ++t) {
            int idx = tid + t * 256;          // 0..511
            int ar  = idx >> 2;               // 0..127
            int ak4 = idx & 3;                // 0..3
            float4 v = *(const float4*)(A + (size_t)(brow + ar) * K + k0 + ak4 * 4);
            As[ak4 * 4 + 0][ar] = v.x;
            As[ak4 * 4 + 1][ar] = v.y;
            As[ak4 * 4 + 2][ar] = v.z;
            As[ak4 * 4 + 3][ar] = v.w;
        }
        // B tile: 16x128 -> 512 float4, 2 per thread
        #pragma unroll
        for (int t = 0; t < 2; ++t) {
            int idx = tid + t * 256;
            int br  = idx >> 5;               // 0..15
            int bc4 = idx & 31;               // 0..31
            *(float4*)&Bs[br][bc4 * 4] =
                *(const float4*)(Bw + (size_t)(k0 + br) * N + bcol + bc4 * 4);
        }
        __syncthreads();

        #pragma unroll
        for (int kk = 0; kk < BK; ++kk) {
            float ra[TM], rb[TN];
            #pragma unroll
            for (int i = 0; i < TM; ++i) ra[i] = As[kk][trow + i];
            #pragma unroll
            for (int j = 0; j < TN; ++j) rb[j] = Bs[kk][tcol + j];
            #pragma unroll
            for (int i = 0; i < TM; ++i)
                #pragma unroll
                for (int j = 0; j < TN; ++j)
                    acc[i][j] += ra[i] * rb[j];
        }
        __syncthreads();
    }

    // epilogue: + x + cb
    #pragma unroll
    for (int i = 0; i < TM; ++i) {
        int r = brow + trow + i;
        #pragma unroll
        for (int j = 0; j < TN; j += 4) {
            int c = bcol + tcol + j;
            float4 xv = *(const float4*)(X + (size_t)r * N + c);
            float4 o;
            o.x = acc[i][j + 0] + xv.x + bias[c + 0];
            o.y = acc[i][j + 1] + xv.y + bias[c + 1];
            o.z = acc[i][j + 2] + xv.z + bias[c + 2];
            o.w = acc[i][j + 3] + xv.w + bias[c + 3];
            *(float4*)(g_rout + (size_t)r * N + c) = o;
        }
    }
}

// ------------------------------------------------------------------
// K3: per-row decisions + gates -> q[row][96]
// block = 16 rows, 256 threads; K-chunks of 64
// cols 0..35 : dec  = routing . dW[t,n,:]   (+db)
// cols 36..47: gate = x . gW[:,t]           (+gb)
// ------------------------------------------------------------------
#define RW3 16
#define KC3 64

__global__ __launch_bounds__(256) void decide_kernel(
    const float* __restrict__ x,
    const float* __restrict__ dW,    // [T,DEP,D]
    const float* __restrict__ db,    // [T,DEP] flat 36
    const float* __restrict__ gW,    // [D,T]
    const float* __restrict__ gb,    // [T]
    const float* __restrict__ ntl)   // [T,DEP] flat 36
{
    __shared__ float sR[RW3][KC3];
    __shared__ float sX[RW3][KC3];
    __shared__ float sW[NCOLS][KC3 + 1];
    __shared__ float sAcc[RW3][NCOLS];

    const int tid  = threadIdx.x;
    const int row0 = blockIdx.x * RW3;
    const int r    = tid >> 4;            // 0..15
    const int cg   = (tid & 15) * 3;      // 0,3,...,45

    float a0 = 0.f, a1 = 0.f, a2 = 0.f;

    for (int k0 = 0; k0 < Dc; k0 += KC3) {
        // routing & x rows: 16x64 floats = 256 float4, 1 each
        {
            int rr = tid >> 4;            // row
            int cc = tid & 15;            // float4 within row
            *(float4*)&sR[rr][cc * 4] =
                *(const float4*)(g_rout + (size_t)(row0 + rr) * Dc + k0 + cc * 4);
            *(float4*)&sX[rr][cc * 4] =
                *(const float4*)(x + (size_t)(row0 + rr) * Dc + k0 + cc * 4);
        }
        // dW chunk: 36 rows x 64
        for (int idx = tid; idx < 36 * 16; idx += 256) {
            int wr = idx >> 4;
            int cc = idx & 15;
            float4 v = *(const float4*)(dW + (size_t)wr * Dc + k0 + cc * 4);
            sW[wr][cc * 4 + 0] = v.x;
            sW[wr][cc * 4 + 1] = v.y;
            sW[wr][cc * 4 + 2] = v.z;
            sW[wr][cc * 4 + 3] = v.w;
        }
        // gW chunk transposed: sW[36+t][kk] = gW[(k0+kk)*T + t]
        for (int idx = tid; idx < Tc * KC3; idx += 256) {
            int t  = idx / KC3;
            int kk = idx % KC3;
            sW[36 + t][kk] = gW[(size_t)(k0 + kk) * Tc + t];
        }
        __syncthreads();

        const float (*srcA)[KC3] = (cg < 36) ? sR : sX;
        #pragma unroll 8
        for (int kk = 0; kk < KC3; ++kk) {
            float a = srcA[r][kk];
            a0 += a * sW[cg + 0][kk];
            a1 += a * sW[cg + 1][kk];
            a2 += a * sW[cg + 2][kk];
        }
        __syncthreads();
    }

    sAcc[r][cg + 0] = a0;
    sAcc[r][cg + 1] = a1;
    sAcc[r][cg + 2] = a2;
    __syncthreads();

    // epilogue: one thread per row
    if (tid < RW3) {
        const int row = row0 + tid;
        float dsig[36];
        #pragma unroll
        for (int c = 0; c < 36; ++c) {
            float temp = softplusf(ntl[c] + 0.5413f);   // TEMP=1
            float z = (sAcc[tid][c] + db[c]) / temp;
            dsig[c] = 1.f / (1.f + expf(-z));
        }
        float g[Tc];
        float mx = -1e30f;
        #pragma unroll
        for (int t = 0; t < Tc; ++t) {
            g[t] = sAcc[tid][36 + t] + gb[t];
            mx = fmaxf(mx, g[t]);
        }
        float sum = 0.f;
        #pragma unroll
        for (int t = 0; t < Tc; ++t) { g[t] = expf(g[t] - mx); sum += g[t]; }
        float inv = 1.f / sum;

        float* qrow = g_q + (size_t)row * 96;
        #pragma unroll
        for (int t = 0; t < Tc; ++t) {
            float wt = g[t] * inv;
            float d0 = dsig[t * 3 + 0];
            float d1 = dsig[t * 3 + 1];
            float d2 = dsig[t * 3 + 2];
            #pragma unroll
            for (int l = 0; l < Lc; ++l) {
                float p = ((l & 4) ? (1.f - d0) : d0)
                        * ((l & 2) ? (1.f - d1) : d1)
                        * ((l & 1) ? (1.f - d2) : d2);
                qrow[t * 8 + l] = wt * p;
            }
        }
    }
}

// ------------------------------------------------------------------
// K4: out = LayerNorm( q @ leaf_out )   fused.
// block = 8 rows x full 1024 cols (256 threads, 4 cols each)
// ------------------------------------------------------------------
#define RW4 8

__global__ __launch_bounds__(256) void out_ln_kernel(
    const float* __restrict__ leaf,   // [96,1024]
    const float* __restrict__ gamma,
    const float* __restrict__ beta,
    float* __restrict__ out)
{
    __shared__ float sQ[RW4][96];
    __shared__ float sO[RW4][Oc];

    const int tid  = threadIdx.x;
    const int row0 = blockIdx.x * RW4;

    for (int idx = tid; idx < RW4 * 96; idx += 256)
        sQ[idx / 96][idx % 96] = g_q[(size_t)(row0 + idx / 96) * 96 + (idx % 96)];
    __syncthreads();

    float acc[RW4][4];
    #pragma unroll
    for (int r = 0; r < RW4; ++r)
        #pragma unroll
        for (int j = 0; j < 4; ++j) acc[r][j] = 0.f;

    #pragma unroll 4
    for (int i = 0; i < 96; ++i) {
        float lf[4];
        #pragma unroll
        for (int j = 0; j < 4; ++j)
            lf[j] = leaf[(size_t)i * Oc + tid + j * 256];
        #pragma unroll
        for (int r = 0; r < RW4; ++r) {
            float qa = sQ[r][i];
            #pragma unroll
            for (int j = 0; j < 4; ++j) acc[r][j] += qa * lf[j];
        }
    }

    #pragma unroll
    for (int r = 0; r < RW4; ++r)
        #pragma unroll
        for (int j = 0; j < 4; ++j)
            sO[r][tid + j * 256] = acc[r][j];
    __syncthreads();

    // LayerNorm: warp per row
    const int wid  = tid >> 5;
    const int lane = tid & 31;

    float s = 0.f;
    #pragma unroll
    for (int k = 0; k < Oc / 32; ++k) s += sO[wid][lane + 32 * k];
    #pragma unroll
    for (int off = 16; off > 0; off >>= 1) s += __shfl_xor_sync(0xFFFFFFFFu, s, off);
    const float mu = s * (1.f / Oc);

    float v = 0.f;
    #pragma unroll
    for (int k = 0; k < Oc / 32; ++k) {
        float d = sO[wid][lane + 32 * k] - mu;
        v += d * d;
    }
    #pragma unroll
    for (int off = 16; off > 0; off >>= 1) v += __shfl_xor_sync(0xFFFFFFFFu, v, off);
    const float rstd = rsqrtf(v * (1.f / Oc) + 1e-5f);

    float* orow = out + (size_t)(row0 + wid) * Oc;
    #pragma unroll
    for (int k = 0; k < Oc / 32; ++k) {
        int c = lane + 32 * k;
        orow[c] = (sO[wid][c] - mu) * rstd * gamma[c] + beta[c];
    }
}

// ------------------------------------------------------------------
// launch
// ------------------------------------------------------------------
extern "C" void kernel_launch(void* const* d_in, const int* in_sizes, int n_in,
                              void* d_out, int out_size)
{
    const float* x     = (const float*)d_in[0];
    const float* cW    = (const float*)d_in[1];
    const float* cb    = (const float*)d_in[2];
    const float* dW    = (const float*)d_in[3];
    const float* db    = (const float*)d_in[4];
    const float* leaf  = (const float*)d_in[5];
    const float* gW    = (const float*)d_in[6];
    const float* gb    = (const float*)d_in[7];
    const float* ntl   = (const float*)d_in[8];
    const float* gamma = (const float*)d_in[9];
    const float* beta  = (const float*)d_in[10];
    float* out = (float*)d_out;

    ema_kernel<<<dim3(Dc / 256, Bc), 256>>>(x);
    sgemm_routing<<<dim3(Oc / BN, Mrows / BM), 256>>>(cW, x, cb);
    decide_kernel<<<Mrows / RW3, 256>>>(x, dW, db, gW, gb, ntl);
    out_ln_kernel<<<Mrows / RW4, 256>>>(leaf, gamma, beta, out);
}

// round 4
// speedup vs baseline: 2.5186x; 2.5186x over previous
#include <cuda_runtime.h>
#include <math.h>

// Problem constants
#define Bc   8
#define Sc   512
#define Dc   1024
#define Oc   1024
#define Tc   12
#define Lc   8
#define Mrows (Bc*Sc)          // 4096
#define NDEC 36                // T*DEP
#define DECAYF 0.9f

typedef unsigned long long u64;

// ------------------------------------------------------------------
// Scratch (allocation-free: device globals)
// ------------------------------------------------------------------
__device__ float g_W2p[4][NDEC * Dc];   // K-split partials of W2^T
__device__ float g_W2t[NDEC * Dc];      // W2^T [36][1024]
__device__ float g_gWt[Tc * Dc];        // gW^T [12][1024]
__device__ float g_bias2[NDEC];         // dW @ cb
__device__ float g_uvg[Mrows * 96];     // per-row: v(36) u(36) g(12) pad(12)
__device__ float g_dec[Mrows * NDEC];   // sigmoid decision values

// ------------------------------------------------------------------
// f32x2 packed-FMA helpers (sm_100a+)
// ------------------------------------------------------------------
__device__ __forceinline__ u64 pack2(float x, float y) {
    u64 r; asm("mov.b64 %0, {%1,%2};" : "=l"(r) : "f"(x), "f"(y)); return r;
}
__device__ __forceinline__ void unpack2(u64 v, float& x, float& y) {
    asm("mov.b64 {%0,%1}, %2;" : "=f"(x), "=f"(y) : "l"(v));
}
__device__ __forceinline__ void fma2(u64& d, u64 a, u64 b) {
    asm("fma.rn.f32x2 %0, %1, %2, %0;" : "+l"(d) : "l"(a), "l"(b));
}

__device__ __forceinline__ float softplusf(float v) {
    return (v > 20.f) ? v : log1pf(expf(v));
}

// ------------------------------------------------------------------
// K0a: W2^T partials.  W2t[tn][e] = sum_d cW[e][d]*dW[tn][d]
// grid (16 e-chunks, 4 k-parts), 256 threads
// ------------------------------------------------------------------
__global__ __launch_bounds__(256) void w2_partial(
    const float* __restrict__ cW, const float* __restrict__ dW)
{
    __shared__ float s_cWT[64][68];   // [kk][e_local]
    __shared__ float s_dW[NDEC][68];  // [tn][kk]

    const int tid = threadIdx.x;
    const int e0  = blockIdx.x * 64;
    const int kb  = blockIdx.y * 256;
    const int el  = tid & 63;
    const int tg  = tid >> 6;         // 0..3 -> 9 tn each

    float acc[9];
    #pragma unroll
    for (int j = 0; j < 9; ++j) acc[j] = 0.f;

    for (int ki = 0; ki < 4; ++ki) {
        const int k0 = kb + ki * 64;
        // cW tile 64e x 64k, store transposed
        #pragma unroll
        for (int t = 0; t < 4; ++t) {
            int idx = tid + t * 256;            // 0..1023
            int er = idx >> 4, cc = idx & 15;
            float4 v = *(const float4*)(cW + (size_t)(e0 + er) * Dc + k0 + cc * 4);
            s_cWT[cc * 4 + 0][er] = v.x;
            s_cWT[cc * 4 + 1][er] = v.y;
            s_cWT[cc * 4 + 2][er] = v.z;
            s_cWT[cc * 4 + 3][er] = v.w;
        }
        // dW tile 36 x 64
        for (int idx = tid; idx < NDEC * 16; idx += 256) {
            int wr = idx >> 4, cc = idx & 15;
            float4 v = *(const float4*)(dW + (size_t)wr * Dc + k0 + cc * 4);
            s_dW[wr][cc * 4 + 0] = v.x;
            s_dW[wr][cc * 4 + 1] = v.y;
            s_dW[wr][cc * 4 + 2] = v.z;
            s_dW[wr][cc * 4 + 3] = v.w;
        }
        __syncthreads();

        #pragma unroll 4
        for (int kk = 0; kk < 64; ++kk) {
            float a = s_cWT[kk][el];
            #pragma unroll
            for (int j = 0; j < 9; ++j)
                acc[j] += a * s_dW[tg * 9 + j][kk];
        }
        __syncthreads();
    }

    #pragma unroll
    for (int j = 0; j < 9; ++j) {
        int tn = tg * 9 + j;
        g_W2p[blockIdx.y][(tn << 10) + e0 + el] = acc[j];
    }
}

// ------------------------------------------------------------------
// K0b: reduce W2 partials + transpose gW
// ------------------------------------------------------------------
__global__ __launch_bounds__(256) void w2_reduce(const float* __restrict__ gW)
{
    int i = blockIdx.x * 256 + threadIdx.x;
    if (i < NDEC * Dc) {
        g_W2t[i] = ((g_W2p[0][i] + g_W2p[1][i]) + g_W2p[2][i]) + g_W2p[3][i];
    } else {
        int j = i - NDEC * Dc;          // 0 .. 12*1024-1
        if (j < Tc * Dc) {
            int t = j >> 10, e = j & 1023;
            g_gWt[j] = gW[(size_t)e * Tc + t];
        }
    }
}

// ------------------------------------------------------------------
// K0c: bias2[tn] = dot(cb, dW[tn])
// ------------------------------------------------------------------
__global__ __launch_bounds__(256) void bias2_kernel(
    const float* __restrict__ cb, const float* __restrict__ dW)
{
    __shared__ float red[8];
    int tid = threadIdx.x;
    float4 c = ((const float4*)cb)[tid];
    float4 w = ((const float4*)(dW + (size_t)blockIdx.x * Dc))[tid];
    float p = c.x * w.x + c.y * w.y + c.z * w.z + c.w * w.w;
    #pragma unroll
    for (int off = 16; off > 0; off >>= 1) p += __shfl_xor_sync(~0u, p, off);
    if ((tid & 31) == 0) red[tid >> 5] = p;
    __syncthreads();
    if (tid == 0) {
        float s = 0.f;
        #pragma unroll
        for (int wgi = 0; wgi < 8; ++wgi) s += red[wgi];
        g_bias2[blockIdx.x] = s;
    }
}

// ------------------------------------------------------------------
// K2: uvg[row][c] = x[row] . W[c]  for 96 cols
//   c in [0,36)  -> dW rows      (v)
//   c in [36,72) -> W2t rows     (u)
//   c in [72,84) -> gWt rows     (g)
//   c in [84,96) -> zero (pad)
// 32 rows/block, 128 blocks, 256 threads.
// Thread = 1 row x 6 column-PAIRS; weight pair is a natural LDS.64,
// x broadcast-packed (x,x) once per kk.  smem = 32 KB (static-ok).
// ------------------------------------------------------------------
__global__ __launch_bounds__(256) void uvg_kernel(
    const float* __restrict__ x, const float* __restrict__ dW)
{
    __shared__ __align__(16) float sXT[64][32];   // [kk][row]
    __shared__ __align__(16) float sW[64][96];    // [kk][col]

    const int tid  = threadIdx.x;
    const int row0 = blockIdx.x * 32;
    const int r    = tid >> 3;         // 0..31  (row)
    const int c    = tid & 7;          // col-pair groups c + 8j

    u64 acc2[6];
    #pragma unroll
    for (int j = 0; j < 6; ++j) acc2[j] = 0ull;

    for (int k0 = 0; k0 < Dc; k0 += 64) {
        // x tile 32 rows x 64 k, transposed
        #pragma unroll
        for (int t = 0; t < 2; ++t) {
            int idx = tid + t * 256;     // 0..511
            int rr = idx >> 4, cc = idx & 15;
            float4 v = *(const float4*)(x + (size_t)(row0 + rr) * Dc + k0 + cc * 4);
            sXT[cc * 4 + 0][rr] = v.x;
            sXT[cc * 4 + 1][rr] = v.y;
            sXT[cc * 4 + 2][rr] = v.z;
            sXT[cc * 4 + 3][rr] = v.w;
        }
        // weights 96 x 64, transposed into [kk][col]
        #pragma unroll
        for (int t = 0; t < 6; ++t) {
            int idx = tid + t * 256;     // 0..1535
            int wr = idx >> 4, cc = idx & 15;
            float4 v;
            if (wr < NDEC)
                v = *(const float4*)(dW + (size_t)wr * Dc + k0 + cc * 4);
            else if (wr < 72)
                v = *(const float4*)(g_W2t + (size_t)(wr - 36) * Dc + k0 + cc * 4);
            else if (wr < 84)
                v = *(const float4*)(g_gWt + (size_t)(wr - 72) * Dc + k0 + cc * 4);
            else
                v = make_float4(0.f, 0.f, 0.f, 0.f);
            sW[cc * 4 + 0][wr] = v.x;
            sW[cc * 4 + 1][wr] = v.y;
            sW[cc * 4 + 2][wr] = v.z;
            sW[cc * 4 + 3][wr] = v.w;
        }
        __syncthreads();

        #pragma unroll 4
        for (int kk = 0; kk < 64; ++kk) {
            float xs = sXT[kk][r];
            u64 xa = pack2(xs, xs);
            #pragma unroll
            for (int j = 0; j < 6; ++j)
                fma2(acc2[j], xa, *(const u64*)&sW[kk][2 * (c + 8 * j)]);
        }
        __syncthreads();
    }

    float* qrow = g_uvg + (size_t)(row0 + r) * 96;
    #pragma unroll
    for (int j = 0; j < 6; ++j) {
        float a0, a1; unpack2(acc2[j], a0, a1);
        qrow[2 * (c + 8 * j) + 0] = a0;
        qrow[2 * (c + 8 * j) + 1] = a1;
    }
}

// ------------------------------------------------------------------
// K3: per-(b,tn) causal scan of u -> sigmoid decision values.
// decE[b,s,tn] = 0.1 * (1/(g^s+1e-8)) * sum_{j<=s} g^j * u[b,j-1,tn]
// z = (v + decE + db + bias2)/temp ; g_dec = sigmoid(z)
// grid 8 (b), 288 threads = 36 tn x 8 s-chunks of 64
// ------------------------------------------------------------------
__global__ __launch_bounds__(288) void scan_kernel(
    const float* __restrict__ db, const float* __restrict__ ntl)
{
    __shared__ float part[8][NDEC];

    const int tid = threadIdx.x;
    const int b   = blockIdx.x;
    const int tn  = tid % NDEC;
    const int ch  = tid / NDEC;        // 0..7
    const int s0  = ch * 64;

    const double pd0 = pow(0.9, (double)s0);

    // pass 1: chunk partial sums of y_s = g^s * u[b,s-1,tn]
    {
        double pd = pd0;
        float sum = 0.f;
        for (int i = 0; i < 64; ++i) {
            int s = s0 + i;
            float pw = (float)pd;
            if (s >= 1) {
                float up = g_uvg[(size_t)(b * Sc + s - 1) * 96 + 36 + tn];
                sum += up * pw;
            }
            pd *= 0.9;
        }
        part[ch][tn] = sum;
    }
    __syncthreads();

    // exclusive scan over the 8 chunks (thread per tn)
    if (tid < NDEC) {
        float run = 0.f;
        #pragma unroll
        for (int cch = 0; cch < 8; ++cch) {
            float t = part[cch][tid];
            part[cch][tid] = run;
            run += t;
        }
    }
    __syncthreads();

    // pass 2: emit sigmoid(z)
    {
        const float invT = 1.f / softplusf(ntl[tn] + 0.5413f);
        const float bias = db[tn] + g_bias2[tn];
        double pd = pd0;
        float C = part[ch][tn];
        for (int i = 0; i < 64; ++i) {
            int s = s0 + i;
            int row = b * Sc + s;
            float pw = (float)pd;
            if (s >= 1) {
                float up = g_uvg[(size_t)(row - 1) * 96 + 36 + tn];
                C += up * pw;
            }
            float recip = 1.0f / (pw + 1e-8f);
            float decE  = 0.1f * C * recip;
            float v     = g_uvg[(size_t)row * 96 + tn];
            float z     = (v + decE + bias) * invT;
            g_dec[(size_t)row * NDEC + tn] = 1.f / (1.f + expf(-z));
            pd *= 0.9;
        }
    }
}

// ------------------------------------------------------------------
// K5: fused q-construction + out = q @ leaf + LayerNorm
// 16 rows/block, 512 threads (2 cols each), 256 blocks; f32x2 FMAs.
// Phase 0 parallelized over 192 threads (one per (row, tree)).
// ------------------------------------------------------------------
__global__ __launch_bounds__(512) void out_ln_kernel(
    const float* __restrict__ leaf,    // [96][1024]
    const float* __restrict__ gb,
    const float* __restrict__ gamma,
    const float* __restrict__ beta,
    float* __restrict__ out)
{
    __shared__ __align__(16) float sQT[96][16];     // [leafcol][row]
    __shared__ float sRed[16][16][2];               // [row][warp][sum,sumsq]
    __shared__ float sMu[16], sRstd[16];

    const int tid  = threadIdx.x;
    const int row0 = blockIdx.x * 16;

    // phase 0: 192 threads, one per (row, tree).
    // Each redundantly computes its row's 12-gate softmax (cheap) and
    // fills its tree's 8 leaf slots.
    if (tid < 192) {
        const int rr  = tid >> 4;          // wrong split would be tid/12; use row-major:
    }
    if (tid < 192) {
        const int row_l = tid / Tc;        // 0..15
        const int t     = tid % Tc;        // 0..11
        const int row   = row0 + row_l;

        float g[Tc];
        float mx = -1e30f;
        #pragma unroll
        for (int tt = 0; tt < Tc; ++tt) {
            g[tt] = g_uvg[(size_t)row * 96 + 72 + tt] + gb[tt];
            mx = fmaxf(mx, g[tt]);
        }
        float sum = 0.f;
        #pragma unroll
        for (int tt = 0; tt < Tc; ++tt) { g[tt] = expf(g[tt] - mx); sum += g[tt]; }
        const float wt = g[t] / sum;

        const float d0 = g_dec[(size_t)row * NDEC + t * 3 + 0];
        const float d1 = g_dec[(size_t)row * NDEC + t * 3 + 1];
        const float d2 = g_dec[(size_t)row * NDEC + t * 3 + 2];
        #pragma unroll
        for (int l = 0; l < Lc; ++l) {
            float p = ((l & 4) ? (1.f - d0) : d0)
                    * ((l & 2) ? (1.f - d1) : d1)
                    * ((l & 1) ? (1.f - d2) : d2);
            sQT[t * 8 + l][row_l] = wt * p;
        }
    }
    __syncthreads();

    // GEMM: 16 rows x 2 cols per thread, f32x2 over row pairs
    const float2* leaf2 = (const float2*)leaf;
    u64 acc2[8][2];
    #pragma unroll
    for (int j = 0; j < 8; ++j) { acc2[j][0] = 0ull; acc2[j][1] = 0ull; }

    #pragma unroll 4
    for (int i = 0; i < 96; ++i) {
        float2 lf = leaf2[(size_t)i * 512 + tid];
        u64 lx = pack2(lf.x, lf.x);
        u64 ly = pack2(lf.y, lf.y);
        const u64* qp = (const u64*)&sQT[i][0];   // 8 row-pairs
        #pragma unroll
        for (int j = 0; j < 8; ++j) {
            u64 q2 = qp[j];
            fma2(acc2[j][0], q2, lx);
            fma2(acc2[j][1], q2, ly);
        }
    }

    // unpack accumulators: acc[r][c]
    float acc[16][2];
    #pragma unroll
    for (int j = 0; j < 8; ++j) {
        unpack2(acc2[j][0], acc[2 * j][0], acc[2 * j + 1][0]);
        unpack2(acc2[j][1], acc[2 * j][1], acc[2 * j + 1][1]);
    }

    // LayerNorm reductions
    const int wid  = tid >> 5;
    const int lane = tid & 31;
    #pragma unroll
    for (int r = 0; r < 16; ++r) {
        float s  = acc[r][0] + acc[r][1];
        float sq = acc[r][0] * acc[r][0] + acc[r][1] * acc[r][1];
        #pragma unroll
        for (int off = 16; off > 0; off >>= 1) {
            s  += __shfl_xor_sync(~0u, s,  off);
            sq += __shfl_xor_sync(~0u, sq, off);
        }
        if (lane == 0) { sRed[r][wid][0] = s; sRed[r][wid][1] = sq; }
    }
    __syncthreads();

    if (wid < 16) {
        // warp w reduces row w across 16 warps
        float s  = (lane < 16) ? sRed[wid][lane][0] : 0.f;
        float sq = (lane < 16) ? sRed[wid][lane][1] : 0.f;
        #pragma unroll
        for (int off = 8; off > 0; off >>= 1) {
            s  += __shfl_xor_sync(~0u, s,  off);
            sq += __shfl_xor_sync(~0u, sq, off);
        }
        if (lane == 0) {
            float mu  = s * (1.f / Oc);
            float var = sq * (1.f / Oc) - mu * mu;
            sMu[wid]   = mu;
            sRstd[wid] = rsqrtf(var + 1e-5f);
        }
    }
    __syncthreads();

    const float2 g2 = ((const float2*)gamma)[tid];
    const float2 b2 = ((const float2*)beta)[tid];
    float2* out2 = (float2*)out;
    #pragma unroll
    for (int r = 0; r < 16; ++r) {
        float mu = sMu[r], rstd = sRstd[r];
        float2 o;
        o.x = (acc[r][0] - mu) * rstd * g2.x + b2.x;
        o.y = (acc[r][1] - mu) * rstd * g2.y + b2.y;
        out2[(size_t)(row0 + r) * 512 + tid] = o;
    }
}

// ------------------------------------------------------------------
// launch
// ------------------------------------------------------------------
extern "C" void kernel_launch(void* const* d_in, const int* in_sizes, int n_in,
                              void* d_out, int out_size)
{
    const float* x     = (const float*)d_in[0];
    const float* cW    = (const float*)d_in[1];
    const float* cb    = (const float*)d_in[2];
    const float* dW    = (const float*)d_in[3];
    const float* db    = (const float*)d_in[4];
    const float* leaf  = (const float*)d_in[5];
    const float* gW    = (const float*)d_in[6];
    const float* gb    = (const float*)d_in[7];
    const float* ntl   = (const float*)d_in[8];
    const float* gamma = (const float*)d_in[9];
    const float* beta  = (const float*)d_in[10];
    float* out = (float*)d_out;

    w2_partial<<<dim3(16, 4), 256>>>(cW, dW);
    w2_reduce<<<192, 256>>>(gW);
    bias2_kernel<<<NDEC, 256>>>(cb, dW);
    uvg_kernel<<<128, 256>>>(x, dW);
    scan_kernel<<<Bc, 288>>>(db, ntl);
    out_ln_kernel<<<Mrows / 16, 512>>>(leaf, gb, gamma, beta, out);
}

// round 5
// speedup vs baseline: 3.7579x; 1.4921x over previous
#include <cuda_runtime.h>
#include <math.h>

// Problem constants
#define Bc   8
#define Sc   512
#define Dc   1024
#define Oc   1024
#define Tc   12
#define Lc   8
#define Mrows (Bc*Sc)          // 4096
#define NDEC 36                // T*DEP
#define NSPLIT 8               // split-K factor for uvg

typedef unsigned long long u64;

// ------------------------------------------------------------------
// Scratch (allocation-free: device globals)
// ------------------------------------------------------------------
__device__ float g_W2p[4][NDEC * Dc];       // K-split partials of W2^T
__device__ float g_W2t[NDEC * Dc];          // W2^T [36][1024]
__device__ float g_gWt[Tc * Dc];            // gW^T [12][1024]
__device__ float g_bias2[NDEC];             // dW @ cb
__device__ float g_uvp[NSPLIT][Mrows * 96]; // split-K partials of uvg
__device__ float g_uvg[Mrows * 96];         // per-row: v(36) u(36) g(12) pad(12)
__device__ float g_dec[Mrows * NDEC];       // sigmoid decision values

// ------------------------------------------------------------------
// f32x2 packed-FMA helpers (sm_100a+)
// ------------------------------------------------------------------
__device__ __forceinline__ u64 pack2(float x, float y) {
    u64 r; asm("mov.b64 %0, {%1,%2};" : "=l"(r) : "f"(x), "f"(y)); return r;
}
__device__ __forceinline__ void unpack2(u64 v, float& x, float& y) {
    asm("mov.b64 {%0,%1}, %2;" : "=f"(x), "=f"(y) : "l"(v));
}
__device__ __forceinline__ void fma2(u64& d, u64 a, u64 b) {
    asm("fma.rn.f32x2 %0, %1, %2, %0;" : "+l"(d) : "l"(a), "l"(b));
}

__device__ __forceinline__ float softplusf(float v) {
    return (v > 20.f) ? v : log1pf(expf(v));
}

// ------------------------------------------------------------------
// K0a: W2^T partials.  W2t[tn][e] = sum_d cW[e][d]*dW[tn][d]
// grid (16 e-chunks, 4 k-parts), 256 threads
// ------------------------------------------------------------------
__global__ __launch_bounds__(256) void w2_partial(
    const float* __restrict__ cW, const float* __restrict__ dW)
{
    __shared__ float s_cWT[64][68];   // [kk][e_local]
    __shared__ float s_dW[NDEC][68];  // [tn][kk]

    const int tid = threadIdx.x;
    const int e0  = blockIdx.x * 64;
    const int kb  = blockIdx.y * 256;
    const int el  = tid & 63;
    const int tg  = tid >> 6;         // 0..3 -> 9 tn each

    float acc[9];
    #pragma unroll
    for (int j = 0; j < 9; ++j) acc[j] = 0.f;

    for (int ki = 0; ki < 4; ++ki) {
        const int k0 = kb + ki * 64;
        #pragma unroll
        for (int t = 0; t < 4; ++t) {
            int idx = tid + t * 256;            // 0..1023
            int er = idx >> 4, cc = idx & 15;
            float4 v = *(const float4*)(cW + (size_t)(e0 + er) * Dc + k0 + cc * 4);
            s_cWT[cc * 4 + 0][er] = v.x;
            s_cWT[cc * 4 + 1][er] = v.y;
            s_cWT[cc * 4 + 2][er] = v.z;
            s_cWT[cc * 4 + 3][er] = v.w;
        }
        for (int idx = tid; idx < NDEC * 16; idx += 256) {
            int wr = idx >> 4, cc = idx & 15;
            float4 v = *(const float4*)(dW + (size_t)wr * Dc + k0 + cc * 4);
            s_dW[wr][cc * 4 + 0] = v.x;
            s_dW[wr][cc * 4 + 1] = v.y;
            s_dW[wr][cc * 4 + 2] = v.z;
            s_dW[wr][cc * 4 + 3] = v.w;
        }
        __syncthreads();

        #pragma unroll 4
        for (int kk = 0; kk < 64; ++kk) {
            float a = s_cWT[kk][el];
            #pragma unroll
            for (int j = 0; j < 9; ++j)
                acc[j] += a * s_dW[tg * 9 + j][kk];
        }
        __syncthreads();
    }

    #pragma unroll
    for (int j = 0; j < 9; ++j) {
        int tn = tg * 9 + j;
        g_W2p[blockIdx.y][(tn << 10) + e0 + el] = acc[j];
    }
}

// ------------------------------------------------------------------
// K0b: reduce W2 partials + transpose gW
// ------------------------------------------------------------------
__global__ __launch_bounds__(256) void w2_reduce(const float* __restrict__ gW)
{
    int i = blockIdx.x * 256 + threadIdx.x;
    if (i < NDEC * Dc) {
        g_W2t[i] = ((g_W2p[0][i] + g_W2p[1][i]) + g_W2p[2][i]) + g_W2p[3][i];
    } else {
        int j = i - NDEC * Dc;          // 0 .. 12*1024-1
        if (j < Tc * Dc) {
            int t = j >> 10, e = j & 1023;
            g_gWt[j] = gW[(size_t)e * Tc + t];
        }
    }
}

// ------------------------------------------------------------------
// K0c: bias2[tn] = dot(cb, dW[tn])
// ------------------------------------------------------------------
__global__ __launch_bounds__(256) void bias2_kernel(
    const float* __restrict__ cb, const float* __restrict__ dW)
{
    __shared__ float red[8];
    int tid = threadIdx.x;
    float4 c = ((const float4*)cb)[tid];
    float4 w = ((const float4*)(dW + (size_t)blockIdx.x * Dc))[tid];
    float p = c.x * w.x + c.y * w.y + c.z * w.z + c.w * w.w;
    #pragma unroll
    for (int off = 16; off > 0; off >>= 1) p += __shfl_xor_sync(~0u, p, off);
    if ((tid & 31) == 0) red[tid >> 5] = p;
    __syncthreads();
    if (tid == 0) {
        float s = 0.f;
        #pragma unroll
        for (int wgi = 0; wgi < 8; ++wgi) s += red[wgi];
        g_bias2[blockIdx.x] = s;
    }
}

// ------------------------------------------------------------------
// K2: uvg partials.  uvg[row][c] = x[row] . W[c], 96 cols:
//   [0,36) dW rows (v) | [36,72) W2t (u) | [72,84) gWt (g) | [84,96) zero
// Split-K by 8: grid (32 row-blocks, 8 k-splits), 256 threads.
// Block tile: 128 rows x 96 cols x K=128 (4 chunks of 32).
// Thread tile: 4 rows x 6 col-pairs = 24 FFMA2/kk from 5 LDS.128.
// x stored duplicated (x,x); weights stored as col-pairs.
// ------------------------------------------------------------------
#define CHK 32

__global__ __launch_bounds__(256) void uvg_kernel(
    const float* __restrict__ x, const float* __restrict__ dW)
{
    __shared__ __align__(16) float2 sXd[CHK][130];  // [kk][row] dup, pad 2
    __shared__ __align__(16) float2 sWp[CHK][50];   // [kk][pair], pad 2

    const int tid   = threadIdx.x;
    const int row0  = blockIdx.x * 128;
    const int kbase = blockIdx.y * 128;
    const int ty    = tid >> 3;        // 0..31 -> rows 4ty..4ty+3
    const int tx    = tid & 7;         // 0..7  -> pairs 6tx..6tx+5

    u64 acc[4][6];
    #pragma unroll
    for (int r = 0; r < 4; ++r)
        #pragma unroll
        for (int c = 0; c < 6; ++c) acc[r][c] = 0ull;

    for (int ch = 0; ch < 4; ++ch) {
        const int k0 = kbase + ch * CHK;

        // x tile: 128 rows x 32 k -> duplicated transpose (4 float4/thread)
        #pragma unroll
        for (int t = 0; t < 4; ++t) {
            int idx = tid + t * 256;           // 0..1023
            int r = idx >> 3, k4 = idx & 7;
            float4 v = *(const float4*)(x + (size_t)(row0 + r) * Dc + k0 + k4 * 4);
            sXd[k4 * 4 + 0][r] = make_float2(v.x, v.x);
            sXd[k4 * 4 + 1][r] = make_float2(v.y, v.y);
            sXd[k4 * 4 + 2][r] = make_float2(v.z, v.z);
            sXd[k4 * 4 + 3][r] = make_float2(v.w, v.w);
        }
        // weight tile: 96 cols x 32 k -> pair transpose (3 float4/thread)
        #pragma unroll
        for (int t = 0; t < 3; ++t) {
            int idx = tid + t * 256;           // 0..767
            int c = idx >> 3, k4 = idx & 7;
            float4 v;
            if (c < NDEC)
                v = *(const float4*)(dW + (size_t)c * Dc + k0 + k4 * 4);
            else if (c < 72)
                v = *(const float4*)(g_W2t + (size_t)(c - 36) * Dc + k0 + k4 * 4);
            else if (c < 84)
                v = *(const float4*)(g_gWt + (size_t)(c - 72) * Dc + k0 + k4 * 4);
            else
                v = make_float4(0.f, 0.f, 0.f, 0.f);
            float* dst0 = (float*)&sWp[k4 * 4 + 0][c >> 1] + (c & 1);
            dst0[0]       = v.x;
            dst0[100]     = v.y;   // +1 kk  = 50 float2 = 100 floats
            dst0[200]     = v.z;
            dst0[300]     = v.w;
        }
        __syncthreads();

        #pragma unroll 8
        for (int kk = 0; kk < CHK; ++kk) {
            ulonglong2 xa = *(const ulonglong2*)&sXd[kk][ty * 4];
            ulonglong2 xb = *(const ulonglong2*)&sXd[kk][ty * 4 + 2];
            ulonglong2 w0 = *(const ulonglong2*)&sWp[kk][tx * 6];
            ulonglong2 w1 = *(const ulonglong2*)&sWp[kk][tx * 6 + 2];
            ulonglong2 w2 = *(const ulonglong2*)&sWp[kk][tx * 6 + 4];
            u64 xr[4] = {xa.x, xa.y, xb.x, xb.y};
            u64 wv[6] = {w0.x, w0.y, w1.x, w1.y, w2.x, w2.y};
            #pragma unroll
            for (int r = 0; r < 4; ++r)
                #pragma unroll
                for (int c = 0; c < 6; ++c)
                    fma2(acc[r][c], xr[r], wv[c]);
        }
        __syncthreads();
    }

    // store partials: 4 rows x 6 pairs, STG.64 each
    float* base = g_uvp[blockIdx.y] + (size_t)(row0 + ty * 4) * 96;
    #pragma unroll
    for (int r = 0; r < 4; ++r) {
        #pragma unroll
        for (int c = 0; c < 6; ++c)
            *(u64*)(base + (size_t)r * 96 + 2 * (tx * 6 + c)) = acc[r][c];
    }
}

// ------------------------------------------------------------------
// K2b: reduce split-K partials (float4-wide)
// ------------------------------------------------------------------
__global__ __launch_bounds__(256) void uvg_reduce()
{
    int i = blockIdx.x * 256 + threadIdx.x;   // float4 index, < 98304
    float4 s = make_float4(0.f, 0.f, 0.f, 0.f);
    #pragma unroll
    for (int ks = 0; ks < NSPLIT; ++ks) {
        float4 v = ((const float4*)g_uvp[ks])[i];
        s.x += v.x; s.y += v.y; s.z += v.z; s.w += v.w;
    }
    ((float4*)g_uvg)[i] = s;
}

// ------------------------------------------------------------------
// K3: per-(b,tn) causal scan of u -> sigmoid decision values.
// ------------------------------------------------------------------
__global__ __launch_bounds__(288) void scan_kernel(
    const float* __restrict__ db, const float* __restrict__ ntl)
{
    __shared__ float part[8][NDEC];

    const int tid = threadIdx.x;
    const int b   = blockIdx.x;
    const int tn  = tid % NDEC;
    const int ch  = tid / NDEC;        // 0..7
    const int s0  = ch * 64;

    const double pd0 = pow(0.9, (double)s0);

    {
        double pd = pd0;
        float sum = 0.f;
        for (int i = 0; i < 64; ++i) {
            int s = s0 + i;
            float pw = (float)pd;
            if (s >= 1) {
                float up = g_uvg[(size_t)(b * Sc + s - 1) * 96 + 36 + tn];
                sum += up * pw;
            }
            pd *= 0.9;
        }
        part[ch][tn] = sum;
    }
    __syncthreads();

    if (tid < NDEC) {
        float run = 0.f;
        #pragma unroll
        for (int cch = 0; cch < 8; ++cch) {
            float t = part[cch][tid];
            part[cch][tid] = run;
            run += t;
        }
    }
    __syncthreads();

    {
        const float invT = 1.f / softplusf(ntl[tn] + 0.5413f);
        const float bias = db[tn] + g_bias2[tn];
        double pd = pd0;
        float C = part[ch][tn];
        for (int i = 0; i < 64; ++i) {
            int s = s0 + i;
            int row = b * Sc + s;
            float pw = (float)pd;
            if (s >= 1) {
                float up = g_uvg[(size_t)(row - 1) * 96 + 36 + tn];
                C += up * pw;
            }
            float recip = 1.0f / (pw + 1e-8f);
            float decE  = 0.1f * C * recip;
            float v     = g_uvg[(size_t)row * 96 + tn];
            float z     = (v + decE + bias) * invT;
            g_dec[(size_t)row * NDEC + tn] = 1.f / (1.f + expf(-z));
            pd *= 0.9;
        }
    }
}

// ------------------------------------------------------------------
// K5: fused q-construction + out = q @ leaf + LayerNorm
// 16 rows/block, 512 threads (2 cols each), 256 blocks; f32x2 FMAs.
// ------------------------------------------------------------------
__global__ __launch_bounds__(512) void out_ln_kernel(
    const float* __restrict__ leaf,    // [96][1024]
    const float* __restrict__ gb,
    const float* __restrict__ gamma,
    const float* __restrict__ beta,
    float* __restrict__ out)
{
    __shared__ __align__(16) float sQT[96][16];     // [leafcol][row]
    __shared__ float sRed[16][16][2];               // [row][warp][sum,sumsq]
    __shared__ float sMu[16], sRstd[16];

    const int tid  = threadIdx.x;
    const int row0 = blockIdx.x * 16;

    // phase 0: 192 threads, one per (row, tree)
    if (tid < 192) {
        const int row_l = tid / Tc;        // 0..15
        const int t     = tid % Tc;        // 0..11
        const int row   = row0 + row_l;

        float g[Tc];
        float mx = -1e30f;
        #pragma unroll
        for (int tt = 0; tt < Tc; ++tt) {
            g[tt] = g_uvg[(size_t)row * 96 + 72 + tt] + gb[tt];
            mx = fmaxf(mx, g[tt]);
        }
        float sum = 0.f;
        #pragma unroll
        for (int tt = 0; tt < Tc; ++tt) { g[tt] = expf(g[tt] - mx); sum += g[tt]; }
        const float wt = g[t] / sum;

        const float d0 = g_dec[(size_t)row * NDEC + t * 3 + 0];
        const float d1 = g_dec[(size_t)row * NDEC + t * 3 + 1];
        const float d2 = g_dec[(size_t)row * NDEC + t * 3 + 2];
        #pragma unroll
        for (int l = 0; l < Lc; ++l) {
            float p = ((l & 4) ? (1.f - d0) : d0)
                    * ((l & 2) ? (1.f - d1) : d1)
                    * ((l & 1) ? (1.f - d2) : d2);
            sQT[t * 8 + l][row_l] = wt * p;
        }
    }
    __syncthreads();

    // GEMM: 16 rows x 2 cols per thread, f32x2 over row pairs
    const float2* leaf2 = (const float2*)leaf;
    u64 acc2[8][2];
    #pragma unroll
    for (int j = 0; j < 8; ++j) { acc2[j][0] = 0ull; acc2[j][1] = 0ull; }

    #pragma unroll 4
    for (int i = 0; i < 96; ++i) {
        float2 lf = leaf2[(size_t)i * 512 + tid];
        u64 lx = pack2(lf.x, lf.x);
        u64 ly = pack2(lf.y, lf.y);
        const u64* qp = (const u64*)&sQT[i][0];   // 8 row-pairs
        #pragma unroll
        for (int j = 0; j < 8; ++j) {
            u64 q2 = qp[j];
            fma2(acc2[j][0], q2, lx);
            fma2(acc2[j][1], q2, ly);
        }
    }

    float acc[16][2];
    #pragma unroll
    for (int j = 0; j < 8; ++j) {
        unpack2(acc2[j][0], acc[2 * j][0], acc[2 * j + 1][0]);
        unpack2(acc2[j][1], acc[2 * j][1], acc[2 * j + 1][1]);
    }

    // LayerNorm reductions
    const int wid  = tid >> 5;
    const int lane = tid & 31;
    #pragma unroll
    for (int r = 0; r < 16; ++r) {
        float s  = acc[r][0] + acc[r][1];
        float sq = acc[r][0] * acc[r][0] + acc[r][1] * acc[r][1];
        #pragma unroll
        for (int off = 16; off > 0; off >>= 1) {
            s  += __shfl_xor_sync(~0u, s,  off);
            sq += __shfl_xor_sync(~0u, sq, off);
        }
        if (lane == 0) { sRed[r][wid][0] = s; sRed[r][wid][1] = sq; }
    }
    __syncthreads();

    if (wid < 16) {
        float s  = (lane < 16) ? sRed[wid][lane][0] : 0.f;
        float sq = (lane < 16) ? sRed[wid][lane][1] : 0.f;
        #pragma unroll
        for (int off = 8; off > 0; off >>= 1) {
            s  += __shfl_xor_sync(~0u, s,  off);
            sq += __shfl_xor_sync(~0u, sq, off);
        }
        if (lane == 0) {
            float mu  = s * (1.f / Oc);
            float var = sq * (1.f / Oc) - mu * mu;
            sMu[wid]   = mu;
            sRstd[wid] = rsqrtf(var + 1e-5f);
        }
    }
    __syncthreads();

    const float2 g2 = ((const float2*)gamma)[tid];
    const float2 b2 = ((const float2*)beta)[tid];
    float2* out2 = (float2*)out;
    #pragma unroll
    for (int r = 0; r < 16; ++r) {
        float mu = sMu[r], rstd = sRstd[r];
        float2 o;
        o.x = (acc[r][0] - mu) * rstd * g2.x + b2.x;
        o.y = (acc[r][1] - mu) * rstd * g2.y + b2.y;
        out2[(size_t)(row0 + r) * 512 + tid] = o;
    }
}

// ------------------------------------------------------------------
// launch
// ------------------------------------------------------------------
extern "C" void kernel_launch(void* const* d_in, const int* in_sizes, int n_in,
                              void* d_out, int out_size)
{
    const float* x     = (const float*)d_in[0];
    const float* cW    = (const float*)d_in[1];
    const float* cb    = (const float*)d_in[2];
    const float* dW    = (const float*)d_in[3];
    const float* db    = (const float*)d_in[4];
    const float* leaf  = (const float*)d_in[5];
    const float* gW    = (const float*)d_in[6];
    const float* gb    = (const float*)d_in[7];
    const float* ntl   = (const float*)d_in[8];
    const float* gamma = (const float*)d_in[9];
    const float* beta  = (const float*)d_in[10];
    float* out = (float*)d_out;

    w2_partial<<<dim3(16, 4), 256>>>(cW, dW);
    w2_reduce<<<192, 256>>>(gW);
    bias2_kernel<<<NDEC, 256>>>(cb, dW);
    uvg_kernel<<<dim3(32, NSPLIT), 256>>>(x, dW);
    uvg_reduce<<<384, 256>>>();
    scan_kernel<<<Bc, 288>>>(db, ntl);
    out_ln_kernel<<<Mrows / 16, 512>>>(leaf, gb, gamma, beta, out);
}

// round 7
// speedup vs baseline: 4.3252x; 1.1509x over previous
#include <cuda_runtime.h>
#include <cuda_bf16.h>
#include <math.h>

// Problem constants
#define Bc   8
#define Sc   512
#define Dc   1024
#define Oc   1024
#define Tc   12
#define Lc   8
#define Mrows (Bc*Sc)          // 4096
#define NDEC 36                // T*DEP
#define NSPLIT 4               // split-K for uvg mma

typedef unsigned long long u64;
typedef unsigned int u32;

// ------------------------------------------------------------------
// Scratch (allocation-free: device globals)
// ------------------------------------------------------------------
__device__ float g_W2p[4][NDEC * Dc];       // K-split partials of W2^T
__device__ float g_W2t[NDEC * Dc];          // W2^T [36][1024]
__device__ float g_gWt[Tc * Dc];            // gW^T [12][1024]
__device__ float g_bias2[NDEC];             // dW @ cb
__device__ __nv_bfloat16 g_Wh[96 * Dc];     // weight hi (bf16) [96][1024]
__device__ __nv_bfloat16 g_Wl[96 * Dc];     // weight lo (bf16)
__device__ float g_uvp[NSPLIT][Mrows * 96]; // split-K partials
__device__ float g_uvg[Mrows * 96];         // per-row: v(36) u(36) g(12) pad(12)
__device__ float g_dec[Mrows * NDEC];       // sigmoid decision values

// ------------------------------------------------------------------
// helpers
// ------------------------------------------------------------------
__device__ __forceinline__ u64 pack2(float x, float y) {
    u64 r; asm("mov.b64 %0, {%1,%2};" : "=l"(r) : "f"(x), "f"(y)); return r;
}
__device__ __forceinline__ void unpack2(u64 v, float& x, float& y) {
    asm("mov.b64 {%0,%1}, %2;" : "=f"(x), "=f"(y) : "l"(v));
}
__device__ __forceinline__ void fma2(u64& d, u64 a, u64 b) {
    asm("fma.rn.f32x2 %0, %1, %2, %0;" : "+l"(d) : "l"(a), "l"(b));
}
__device__ __forceinline__ float softplusf(float v) {
    return (v > 20.f) ? v : log1pf(expf(v));
}

// bf16 mma.sync (baseline PTX, works on sm_100)
__device__ __forceinline__ void mma_bf16(
    float& c0, float& c1, float& c2, float& c3,
    u32 a0, u32 a1, u32 a2, u32 a3, u32 b0, u32 b1)
{
    asm volatile(
        "mma.sync.aligned.m16n8k16.row.col.f32.bf16.bf16.f32 "
        "{%0,%1,%2,%3}, {%4,%5,%6,%7}, {%8,%9}, {%0,%1,%2,%3};"
        : "+f"(c0), "+f"(c1), "+f"(c2), "+f"(c3)
        : "r"(a0), "r"(a1), "r"(a2), "r"(a3), "r"(b0), "r"(b1));
}

// hi/lo split of a float into two bf16-in-u16
__device__ __forceinline__ void bf16_split(float v, unsigned short& h, unsigned short& l) {
    __nv_bfloat16 hb = __float2bfloat16(v);
    float lo = v - __bfloat162float(hb);
    h = __bfloat16_as_ushort(hb);
    l = __bfloat16_as_ushort(__float2bfloat16(lo));
}

// ------------------------------------------------------------------
// K0a: W2^T partials.  W2t[tn][e] = sum_d cW[e][d]*dW[tn][d]
// ------------------------------------------------------------------
__global__ __launch_bounds__(256) void w2_partial(
    const float* __restrict__ cW, const float* __restrict__ dW)
{
    __shared__ float s_cWT[64][68];
    __shared__ float s_dW[NDEC][68];

    const int tid = threadIdx.x;
    const int e0  = blockIdx.x * 64;
    const int kb  = blockIdx.y * 256;
    const int el  = tid & 63;
    const int tg  = tid >> 6;

    float acc[9];
    #pragma unroll
    for (int j = 0; j < 9; ++j) acc[j] = 0.f;

    for (int ki = 0; ki < 4; ++ki) {
        const int k0 = kb + ki * 64;
        #pragma unroll
        for (int t = 0; t < 4; ++t) {
            int idx = tid + t * 256;
            int er = idx >> 4, cc = idx & 15;
            float4 v = *(const float4*)(cW + (size_t)(e0 + er) * Dc + k0 + cc * 4);
            s_cWT[cc * 4 + 0][er] = v.x;
            s_cWT[cc * 4 + 1][er] = v.y;
            s_cWT[cc * 4 + 2][er] = v.z;
            s_cWT[cc * 4 + 3][er] = v.w;
        }
        for (int idx = tid; idx < NDEC * 16; idx += 256) {
            int wr = idx >> 4, cc = idx & 15;
            float4 v = *(const float4*)(dW + (size_t)wr * Dc + k0 + cc * 4);
            s_dW[wr][cc * 4 + 0] = v.x;
            s_dW[wr][cc * 4 + 1] = v.y;
            s_dW[wr][cc * 4 + 2] = v.z;
            s_dW[wr][cc * 4 + 3] = v.w;
        }
        __syncthreads();

        #pragma unroll 4
        for (int kk = 0; kk < 64; ++kk) {
            float a = s_cWT[kk][el];
            #pragma unroll
            for (int j = 0; j < 9; ++j)
                acc[j] += a * s_dW[tg * 9 + j][kk];
        }
        __syncthreads();
    }

    #pragma unroll
    for (int j = 0; j < 9; ++j) {
        int tn = tg * 9 + j;
        g_W2p[blockIdx.y][(tn << 10) + e0 + el] = acc[j];
    }
}

// ------------------------------------------------------------------
// K0b: reduce W2 partials + transpose gW
// ------------------------------------------------------------------
__global__ __launch_bounds__(256) void w2_reduce(const float* __restrict__ gW)
{
    int i = blockIdx.x * 256 + threadIdx.x;
    if (i < NDEC * Dc) {
        g_W2t[i] = ((g_W2p[0][i] + g_W2p[1][i]) + g_W2p[2][i]) + g_W2p[3][i];
    } else {
        int j = i - NDEC * Dc;
        if (j < Tc * Dc) {
            int t = j >> 10, e = j & 1023;
            g_gWt[j] = gW[(size_t)e * Tc + t];
        }
    }
}

// ------------------------------------------------------------------
// K0c: bias2[tn] = dot(cb, dW[tn])
// ------------------------------------------------------------------
__global__ __launch_bounds__(256) void bias2_kernel(
    const float* __restrict__ cb, const float* __restrict__ dW)
{
    __shared__ float red[8];
    int tid = threadIdx.x;
    float4 c = ((const float4*)cb)[tid];
    float4 w = ((const float4*)(dW + (size_t)blockIdx.x * Dc))[tid];
    float p = c.x * w.x + c.y * w.y + c.z * w.z + c.w * w.w;
    #pragma unroll
    for (int off = 16; off > 0; off >>= 1) p += __shfl_xor_sync(~0u, p, off);
    if ((tid & 31) == 0) red[tid >> 5] = p;
    __syncthreads();
    if (tid == 0) {
        float s = 0.f;
        #pragma unroll
        for (int wgi = 0; wgi < 8; ++wgi) s += red[wgi];
        g_bias2[blockIdx.x] = s;
    }
}

// ------------------------------------------------------------------
// K0d: bf16 hi/lo split of the 96x1024 weight matrix
//   rows [0,36) dW | [36,72) W2t | [72,84) gWt | [84,96) zero
// ------------------------------------------------------------------
__global__ __launch_bounds__(256) void wsplit_kernel(const float* __restrict__ dW)
{
    int idx = blockIdx.x * 256 + threadIdx.x;   // < 96*1024
    int c = idx >> 10, e = idx & 1023;
    float w;
    if (c < NDEC)      w = dW[(size_t)c * Dc + e];
    else if (c < 72)   w = g_W2t[(size_t)(c - 36) * Dc + e];
    else if (c < 84)   w = g_gWt[(size_t)(c - 72) * Dc + e];
    else               w = 0.f;
    unsigned short h, l;
    bf16_split(w, h, l);
    g_Wh[idx] = __ushort_as_bfloat16(h);
    g_Wl[idx] = __ushort_as_bfloat16(l);
}

// ------------------------------------------------------------------
// K2: uvg = x @ W^T via mma.sync bf16 hi/lo (3 terms).
// grid (32 Mtiles, 4 Ksplit), 256 threads (8 warps = 4M x 2N).
// Block: 128 rows x 96 cols x K=256 slice (8 chunks of 32).
// Warp tile: 2 x m16  x  6 x n8.  Fragments via direct LDS.32
// (rows padded to 20 words -> conflict-free fragment reads).
// ------------------------------------------------------------------
#define XW 20   // padded words per row

__global__ __launch_bounds__(256) void uvg_mma_kernel(const float* __restrict__ x)
{
    __shared__ u32 sXh[128][XW];
    __shared__ u32 sXl[128][XW];
    __shared__ u32 sWh[96][XW];
    __shared__ u32 sWl[96][XW];

    const int tid   = threadIdx.x;
    const int wid   = tid >> 5;
    const int lane  = tid & 31;
    const int row0  = blockIdx.x * 128;
    const int kbase = blockIdx.y * 256;

    const int wm = wid & 3;           // 0..3 -> M offset 32*wm
    const int wn = wid >> 2;          // 0..1 -> N offset 48*wn
    const int mbase = wm * 32;
    const int nbase = wn * 48;
    const int r  = lane >> 2;         // 0..7
    const int cq = lane & 3;          // 0..3

    float acc[2][6][4];
    #pragma unroll
    for (int mt = 0; mt < 2; ++mt)
        #pragma unroll
        for (int nt = 0; nt < 6; ++nt)
            #pragma unroll
            for (int e = 0; e < 4; ++e) acc[mt][nt][e] = 0.f;

    // load indices
    const int xm  = tid >> 3;          // preload row (with t*32 offset pattern below)
    const int xk4 = tid & 7;           // float4 within 32-k chunk
    const int wn_r = tid >> 3;         // weight row base pattern
    const int wseg = tid & 7;          // uint2 seg (8B)

    float4 xv[4];
    uint2 wvh[3], wvl[3];

    // prefetch chunk 0
    {
        const int k0 = kbase;
        #pragma unroll
        for (int t = 0; t < 4; ++t) {
            int m = (tid + t * 256) >> 3;
            xv[t] = *(const float4*)(x + (size_t)(row0 + m) * Dc + k0 + xk4 * 4);
        }
        #pragma unroll
        for (int t = 0; t < 3; ++t) {
            int n = (tid + t * 256) >> 3;
            wvh[t] = *(const uint2*)((const char*)g_Wh + (size_t)n * 2048 + k0 * 2 + wseg * 8);
            wvl[t] = *(const uint2*)((const char*)g_Wl + (size_t)n * 2048 + k0 * 2 + wseg * 8);
        }
    }

    for (int ch = 0; ch < 8; ++ch) {
        // ---- store current chunk to smem ----
        #pragma unroll
        for (int t = 0; t < 4; ++t) {
            int m = (tid + t * 256) >> 3;
            float v[4] = {xv[t].x, xv[t].y, xv[t].z, xv[t].w};
            unsigned short h[4], l[4];
            #pragma unroll
            for (int e = 0; e < 4; ++e) bf16_split(v[e], h[e], l[e]);
            sXh[m][xk4 * 2 + 0] = ((u32)h[1] << 16) | h[0];
            sXh[m][xk4 * 2 + 1] = ((u32)h[3] << 16) | h[2];
            sXl[m][xk4 * 2 + 0] = ((u32)l[1] << 16) | l[0];
            sXl[m][xk4 * 2 + 1] = ((u32)l[3] << 16) | l[2];
        }
        #pragma unroll
        for (int t = 0; t < 3; ++t) {
            int n = (tid + t * 256) >> 3;
            sWh[n][wseg * 2 + 0] = wvh[t].x;
            sWh[n][wseg * 2 + 1] = wvh[t].y;
            sWl[n][wseg * 2 + 0] = wvl[t].x;
            sWl[n][wseg * 2 + 1] = wvl[t].y;
        }
        __syncthreads();

        // ---- prefetch next chunk ----
        if (ch < 7) {
            const int k0 = kbase + (ch + 1) * 32;
            #pragma unroll
            for (int t = 0; t < 4; ++t) {
                int m = (tid + t * 256) >> 3;
                xv[t] = *(const float4*)(x + (size_t)(row0 + m) * Dc + k0 + xk4 * 4);
            }
            #pragma unroll
            for (int t = 0; t < 3; ++t) {
                int n = (tid + t * 256) >> 3;
                wvh[t] = *(const uint2*)((const char*)g_Wh + (size_t)n * 2048 + k0 * 2 + wseg * 8);
                wvl[t] = *(const uint2*)((const char*)g_Wl + (size_t)n * 2048 + k0 * 2 + wseg * 8);
            }
        }

        // ---- compute: 2 k16 groups per chunk ----
        #pragma unroll
        for (int kg = 0; kg < 2; ++kg) {
            const int wb = kg * 8;
            u32 ah[2][4], al[2][4];
            #pragma unroll
            for (int mt = 0; mt < 2; ++mt) {
                const int ra = mbase + mt * 16 + r;
                ah[mt][0] = sXh[ra][wb + cq];
                ah[mt][1] = sXh[ra + 8][wb + cq];
                ah[mt][2] = sXh[ra][wb + cq + 4];
                ah[mt][3] = sXh[ra + 8][wb + cq + 4];
                al[mt][0] = sXl[ra][wb + cq];
                al[mt][1] = sXl[ra + 8][wb + cq];
                al[mt][2] = sXl[ra][wb + cq + 4];
                al[mt][3] = sXl[ra + 8][wb + cq + 4];
            }
            u32 bh[6][2], bl[6][2];
            #pragma unroll
            for (int nt = 0; nt < 6; ++nt) {
                const int n = nbase + nt * 8 + r;
                bh[nt][0] = sWh[n][wb + cq];
                bh[nt][1] = sWh[n][wb + cq + 4];
                bl[nt][0] = sWl[n][wb + cq];
                bl[nt][1] = sWl[n][wb + cq + 4];
            }
            #pragma unroll
            for (int mt = 0; mt < 2; ++mt)
                #pragma unroll
                for (int nt = 0; nt < 6; ++nt) {
                    float* c = acc[mt][nt];
                    mma_bf16(c[0], c[1], c[2], c[3],
                             ah[mt][0], ah[mt][1], ah[mt][2], ah[mt][3],
                             bh[nt][0], bh[nt][1]);
                    mma_bf16(c[0], c[1], c[2], c[3],
                             ah[mt][0], ah[mt][1], ah[mt][2], ah[mt][3],
                             bl[nt][0], bl[nt][1]);
                    mma_bf16(c[0], c[1], c[2], c[3],
                             al[mt][0], al[mt][1], al[mt][2], al[mt][3],
                             bh[nt][0], bh[nt][1]);
                }
        }
        __syncthreads();
    }

    // ---- epilogue: write fp32 partials ----
    float* dst = g_uvp[blockIdx.y];
    #pragma unroll
    for (int mt = 0; mt < 2; ++mt) {
        const int m = row0 + mbase + mt * 16;
        #pragma unroll
        for (int nt = 0; nt < 6; ++nt) {
            const int n = nbase + nt * 8 + cq * 2;
            *(float2*)(dst + (size_t)(m + r) * 96 + n)     = make_float2(acc[mt][nt][0], acc[mt][nt][1]);
            *(float2*)(dst + (size_t)(m + r + 8) * 96 + n) = make_float2(acc[mt][nt][2], acc[mt][nt][3]);
        }
    }
}

// ------------------------------------------------------------------
// K2b: reduce split-K partials (float4-wide)
// ------------------------------------------------------------------
__global__ __launch_bounds__(256) void uvg_reduce()
{
    int i = blockIdx.x * 256 + threadIdx.x;   // float4 index, < 98304
    float4 s = make_float4(0.f, 0.f, 0.f, 0.f);
    #pragma unroll
    for (int ks = 0; ks < NSPLIT; ++ks) {
        float4 v = ((const float4*)g_uvp[ks])[i];
        s.x += v.x; s.y += v.y; s.z += v.z; s.w += v.w;
    }
    ((float4*)g_uvg)[i] = s;
}

// ------------------------------------------------------------------
// K3: per-(b,tn) causal scan of u -> sigmoid decision values.
// ------------------------------------------------------------------
__global__ __launch_bounds__(288) void scan_kernel(
    const float* __restrict__ db, const float* __restrict__ ntl)
{
    __shared__ float part[8][NDEC];

    const int tid = threadIdx.x;
    const int b   = blockIdx.x;
    const int tn  = tid % NDEC;
    const int ch  = tid / NDEC;
    const int s0  = ch * 64;

    const double pd0 = pow(0.9, (double)s0);

    {
        double pd = pd0;
        float sum = 0.f;
        for (int i = 0; i < 64; ++i) {
            int s = s0 + i;
            float pw = (float)pd;
            if (s >= 1) {
                float up = g_uvg[(size_t)(b * Sc + s - 1) * 96 + 36 + tn];
                sum += up * pw;
            }
            pd *= 0.9;
        }
        part[ch][tn] = sum;
    }
    __syncthreads();

    if (tid < NDEC) {
        float run = 0.f;
        #pragma unroll
        for (int cch = 0; cch < 8; ++cch) {
            float t = part[cch][tid];
            part[cch][tid] = run;
            run += t;
        }
    }
    __syncthreads();

    {
        const float invT = 1.f / softplusf(ntl[tn] + 0.5413f);
        const float bias = db[tn] + g_bias2[tn];
        double pd = pd0;
        float C = part[ch][tn];
        for (int i = 0; i < 64; ++i) {
            int s = s0 + i;
            int row = b * Sc + s;
            float pw = (float)pd;
            if (s >= 1) {
                float up = g_uvg[(size_t)(row - 1) * 96 + 36 + tn];
                C += up * pw;
            }
            float recip = 1.0f / (pw + 1e-8f);
            float decE  = 0.1f * C * recip;
            float v     = g_uvg[(size_t)row * 96 + tn];
            float z     = (v + decE + bias) * invT;
            g_dec[(size_t)row * NDEC + tn] = 1.f / (1.f + expf(-z));
            pd *= 0.9;
        }
    }
}

// ------------------------------------------------------------------
// K5: fused q-construction + out = q @ leaf + LayerNorm
// ------------------------------------------------------------------
__global__ __launch_bounds__(512) void out_ln_kernel(
    const float* __restrict__ leaf,
    const float* __restrict__ gb,
    const float* __restrict__ gamma,
    const float* __restrict__ beta,
    float* __restrict__ out)
{
    __shared__ __align__(16) float sQT[96][16];
    __shared__ float sRed[16][16][2];
    __shared__ float sMu[16], sRstd[16];

    const int tid  = threadIdx.x;
    const int row0 = blockIdx.x * 16;

    if (tid < 192) {
        const int row_l = tid / Tc;
        const int t     = tid % Tc;
        const int row   = row0 + row_l;

        float g[Tc];
        float mx = -1e30f;
        #pragma unroll
        for (int tt = 0; tt < Tc; ++tt) {
            g[tt] = g_uvg[(size_t)row * 96 + 72 + tt] + gb[tt];
            mx = fmaxf(mx, g[tt]);
        }
        float sum = 0.f;
        #pragma unroll
        for (int tt = 0; tt < Tc; ++tt) { g[tt] = expf(g[tt] - mx); sum += g[tt]; }
        const float wt = g[t] / sum;

        const float d0 = g_dec[(size_t)row * NDEC + t * 3 + 0];
        const float d1 = g_dec[(size_t)row * NDEC + t * 3 + 1];
        const float d2 = g_dec[(size_t)row * NDEC + t * 3 + 2];
        #pragma unroll
        for (int l = 0; l < Lc; ++l) {
            float p = ((l & 4) ? (1.f - d0) : d0)
                    * ((l & 2) ? (1.f - d1) : d1)
                    * ((l & 1) ? (1.f - d2) : d2);
            sQT[t * 8 + l][row_l] = wt * p;
        }
    }
    __syncthreads();

    const float2* leaf2 = (const float2*)leaf;
    u64 acc2[8][2];
    #pragma unroll
    for (int j = 0; j < 8; ++j) { acc2[j][0] = 0ull; acc2[j][1] = 0ull; }

    #pragma unroll 4
    for (int i = 0; i < 96; ++i) {
        float2 lf = leaf2[(size_t)i * 512 + tid];
        u64 lx = pack2(lf.x, lf.x);
        u64 ly = pack2(lf.y, lf.y);
        const ulonglong2* qp2 = (const ulonglong2*)&sQT[i][0];
        ulonglong2 qa = qp2[0], qb = qp2[1], qc = qp2[2], qd = qp2[3];
        u64 q[8] = {qa.x, qa.y, qb.x, qb.y, qc.x, qc.y, qd.x, qd.y};
        #pragma unroll
        for (int j = 0; j < 8; ++j) {
            fma2(acc2[j][0], q[j], lx);
            fma2(acc2[j][1], q[j], ly);
        }
    }

    float acc[16][2];
    #pragma unroll
    for (int j = 0; j < 8; ++j) {
        unpack2(acc2[j][0], acc[2 * j][0], acc[2 * j + 1][0]);
        unpack2(acc2[j][1], acc[2 * j][1], acc[2 * j + 1][1]);
    }

    const int wid  = tid >> 5;
    const int lane = tid & 31;
    #pragma unroll
    for (int r = 0; r < 16; ++r) {
        float s  = acc[r][0] + acc[r][1];
        float sq = acc[r][0] * acc[r][0] + acc[r][1] * acc[r][1];
        #pragma unroll
        for (int off = 16; off > 0; off >>= 1) {
            s  += __shfl_xor_sync(~0u, s,  off);
            sq += __shfl_xor_sync(~0u, sq, off);
        }
        if (lane == 0) { sRed[r][wid][0] = s; sRed[r][wid][1] = sq; }
    }
    __syncthreads();

    if (wid < 16) {
        float s  = (lane < 16) ? sRed[wid][lane][0] : 0.f;
        float sq = (lane < 16) ? sRed[wid][lane][1] : 0.f;
        #pragma unroll
        for (int off = 8; off > 0; off >>= 1) {
            s  += __shfl_xor_sync(~0u, s,  off);
            sq += __shfl_xor_sync(~0u, sq, off);
        }
        if (lane == 0) {
            float mu  = s * (1.f / Oc);
            float var = sq * (1.f / Oc) - mu * mu;
            sMu[wid]   = mu;
            sRstd[wid] = rsqrtf(var + 1e-5f);
        }
    }
    __syncthreads();

    const float2 g2 = ((const float2*)gamma)[tid];
    const float2 b2 = ((const float2*)beta)[tid];
    float2* out2 = (float2*)out;
    #pragma unroll
    for (int r = 0; r < 16; ++r) {
        float mu = sMu[r], rstd = sRstd[r];
        float2 o;
        o.x = (acc[r][0] - mu) * rstd * g2.x + b2.x;
        o.y = (acc[r][1] - mu) * rstd * g2.y + b2.y;
        out2[(size_t)(row0 + r) * 512 + tid] = o;
    }
}

// ------------------------------------------------------------------
// launch
// ------------------------------------------------------------------
extern "C" void kernel_launch(void* const* d_in, const int* in_sizes, int n_in,
                              void* d_out, int out_size)
{
    const float* x     = (const float*)d_in[0];
    const float* cW    = (const float*)d_in[1];
    const float* cb    = (const float*)d_in[2];
    const float* dW    = (const float*)d_in[3];
    const float* db    = (const float*)d_in[4];
    const float* leaf  = (const float*)d_in[5];
    const float* gW    = (const float*)d_in[6];
    const float* gb    = (const float*)d_in[7];
    const float* ntl   = (const float*)d_in[8];
    const float* gamma = (const float*)d_in[9];
    const float* beta  = (const float*)d_in[10];
    float* out = (float*)d_out;

    w2_partial<<<dim3(16, 4), 256>>>(cW, dW);
    w2_reduce<<<192, 256>>>(gW);
    bias2_kernel<<<NDEC, 256>>>(cb, dW);
    wsplit_kernel<<<384, 256>>>(dW);
    uvg_mma_kernel<<<dim3(32, NSPLIT), 256>>>(x);
    uvg_reduce<<<384, 256>>>();
    scan_kernel<<<Bc, 288>>>(db, ntl);
    out_ln_kernel<<<Mrows / 16, 512>>>(leaf, gb, gamma, beta, out);
}